// round 10
// baseline (speedup 1.0000x reference)
#include <cuda_runtime.h>
#include <math.h>

#define HSZ 1024
#define WSZ 1024
#define NIMG 12            // B*C = 4*3
#define TILE 64            // output tile (64x64), 512 threads
#define NPIX (NIMG * HSZ * WSZ)

// Scratch: pointwise-processed image x4 (after brightness/contrast). ~50MB,
// fits in L2 (126MB) -> K2 reads it mostly at L2 latency.
__device__ float g_x4[NPIX];

// ---------------------------------------------------------------------------
// Compile-time Gaussian weights (KSIZE=15, SIGMA=3) -> FFMA-imm literals.
// ---------------------------------------------------------------------------
__host__ __device__ constexpr double cexp_(double x) {
    double t = 1.0, s = 1.0;
    for (int i = 1; i < 60; ++i) { t *= x / i; s += t; }
    return s;
}
__host__ __device__ constexpr double gsum_() {
    double s = 0.0;
    for (int i = 0; i < 15; ++i) { double d = i - 7; s += cexp_(-d * d / 18.0); }
    return s;
}
__host__ __device__ constexpr float gw_(int k) {
    double d = k - 7; return (float)(cexp_(-d * d / 18.0) / gsum_());
}
#define GWDECL constexpr float GW[15] = {gw_(0), gw_(1), gw_(2),  gw_(3),  gw_(4),  \
    gw_(5),  gw_(6), gw_(7), gw_(8), gw_(9), gw_(10), gw_(11), gw_(12), gw_(13), gw_(14)}

__device__ __forceinline__ float tanh_approx(float x) {
    float y; asm("tanh.approx.f32 %0, %1;" : "=f"(y) : "f"(x));
    return y;
}

// ---------------------------------------------------------------------------
// K1: pointwise chain, 1x per pixel, float4 -> g_x4.
// ---------------------------------------------------------------------------
__global__ __launch_bounds__(256) void pointwise_kernel(
    const float* __restrict__ x, const float* __restrict__ gains,
    const float* __restrict__ p_gamma, const float* __restrict__ p_sb,
    const float* __restrict__ p_hr, const float* __restrict__ p_br,
    const float* __restrict__ p_ct)
{
    const int idx4 = blockIdx.x * 256 + threadIdx.x;
    const int ch   = (idx4 >> 18) % 3;
    const float gain = gains[ch];
    const float gam  = p_gamma[0];
    const float sbv  = p_sb[0], hrv = p_hr[0];
    const float shc  = -(sbv + hrv);
    const float brv  = p_br[0], ctv = p_ct[0];
    const float bc0  = 0.5f + brv;

    float4 v4 = __ldg((const float4*)x + idx4);
    float* v = &v4.x;
    #pragma unroll
    for (int i = 0; i < 4; ++i) {
        float t = __powf(v[i] * gain, gam);                   // WB + gamma
        float hi = fmaf(tanh_approx((t - 0.5f) * 5.f), 0.5f, 0.5f);
        t = fmaf(shc, hi, t + sbv);                           // shadow/highlight
        t = fminf(fmaxf(t, 0.f), 1.f);
        t = fmaf(ctv, t - 0.5f, bc0);                         // brightness/contrast
        v[i] = fminf(fmaxf(t, 0.f), 1.f);
    }
    ((float4*)g_x4)[idx4] = v4;
}

// ---------------------------------------------------------------------------
// K2: blur cascade per 64x64 tile. 512 threads, dynamic smem 55,080 B
// (sB 92x81 + sC 78x81; sD aliases sB) -> 4 CTAs/SM, 64 warps.
//   H1: global g_x4 -> sB [92 x 78]   460 thr: r=tid%92, 5 segs x 16 outputs
//   V1+LCE: sB -> sC [78 x 78]        468 thr: col=tid%78, 6 strips x 13 rows
//            (LCE center read straight from g_x4; zero outside image)
//   H2: sC -> sD [78 x 64]            468 thr: r=tid%78, 6 segs x 11 outputs
//   V2+softness+mask -> out           512 thr: 64 cols x 8 strips x 8 rows
// Strides 81 (mod 32 = 17) and 67 (mod 32 = 3): conflict-free for row-fast
// H-lanes and consecutive-lane V-columns.
// ---------------------------------------------------------------------------
__global__ __launch_bounds__(512, 4) void blur_kernel(
    const float* __restrict__ p_ea, const float* __restrict__ p_soft,
    const float* __restrict__ p_int, const float* __restrict__ p_rot,
    const float* __restrict__ p_hard, float* __restrict__ out)
{
    GWDECL;
    extern __shared__ float smem[];
    float* const sB = smem;                 // 92*81 = 7452
    float* const sC = smem + 7452;          // 78*81 = 6318
    float* const sD = sB;                   // 78*67 = 5226 (alias; sB dead after V1)

    const int tid = threadIdx.x;
    const int img = blockIdx.z;
    const int ty0 = blockIdx.y * TILE;
    const int tx0 = blockIdx.x * TILE;

    const float eav = p_ea[0], sof = p_soft[0];
    const float itn = p_int[0], hrd = p_hard[0];
    float snt, cst;
    sincosf(p_rot[0] * 0.017453292519943295f, &snt, &cst);

    const float* __restrict__ xin = g_x4 + (size_t)img * (HSZ * WSZ);
    // H1 touches rows ty0-14..ty0+77 and cols tx0-14..tx0+79 (window overrun).
    const bool interior = (ty0 >= 14) && (ty0 + 78 <= HSZ) && (tx0 >= 14) && (tx0 + 80 <= WSZ);

    // ---- H1: read g_x4 directly, write sB. 16 outputs/thread, window 30 ----
    if (tid < 460) {
        int r = tid % 92, seg = tid / 92;
        int c0 = seg * 16;
        float acc[16] = {};
        if (interior) {
            const float* __restrict__ a = xin + (ty0 - 14 + r) * WSZ + (tx0 - 14 + c0);
            #pragma unroll
            for (int i = 0; i < 30; ++i) {
                float v = __ldg(a + i);             // overrun cols feed only discarded accs
                #pragma unroll
                for (int k = 0; k < 15; ++k) {
                    int j = i - k;
                    if (j >= 0 && j < 16) acc[j] = fmaf(v, GW[k], acc[j]);
                }
            }
        } else {
            int gy = ty0 - 14 + r;
            bool rowok = (unsigned)gy < HSZ;
            const float* __restrict__ a = xin + gy * WSZ + (tx0 - 14 + c0);
            #pragma unroll
            for (int i = 0; i < 30; ++i) {
                int gx = tx0 - 14 + c0 + i;
                float v = (rowok && (unsigned)gx < WSZ) ? __ldg(a + i) : 0.f;
                #pragma unroll
                for (int k = 0; k < 15; ++k) {
                    int j = i - k;
                    if (j >= 0 && j < 16) acc[j] = fmaf(v, GW[k], acc[j]);
                }
            }
        }
        float* b = &sB[r * 81 + c0];
        #pragma unroll
        for (int j = 0; j < 16; ++j)
            if (c0 + j < 78) b[j] = acc[j];
    }
    __syncthreads();

    // ---- V1 + LCE epilogue: sB -> sC. 13 rows/thread, window 27 ----
    if (tid < 468) {
        int strip = tid / 78, ccol = tid - 78 * strip;
        int r0 = strip * 13;
        const float* b = &sB[r0 * 81 + ccol];
        float acc[13] = {};
        #pragma unroll
        for (int i = 0; i < 27; ++i) {              // rows r0..r0+26 <= 91, all real
            float v = b[i * 81];
            #pragma unroll
            for (int k = 0; k < 15; ++k) {
                int j = i - k;
                if (j >= 0 && j < 13) acc[j] = fmaf(v, GW[k], acc[j]);
            }
        }
        if (interior) {
            const float* __restrict__ ctr = xin + (ty0 - 7 + r0) * WSZ + (tx0 - 7 + ccol);
            #pragma unroll
            for (int j = 0; j < 13; ++j) {
                float a = __ldg(ctr + j * WSZ);
                sC[(r0 + j) * 81 + ccol] = fmaf(eav, a - acc[j], a);  // x + ea*(x - mean)
            }
        } else {
            #pragma unroll
            for (int j = 0; j < 13; ++j) {
                int rr = r0 + j;
                int gy = ty0 - 7 + rr, gx = tx0 - 7 + ccol;
                float val = 0.f;
                if ((unsigned)gy < HSZ && (unsigned)gx < WSZ) {
                    float a = __ldg(xin + gy * WSZ + gx);
                    val = fmaf(eav, a - acc[j], a);
                }
                sC[rr * 81 + ccol] = val;           // zero outside image = blur2 zero-pad
            }
        }
    }
    __syncthreads();

    // ---- H2: sC -> sD. row-fast lanes, 11 outputs/thread, window 25 ----
    if (tid < 468) {
        int r = tid % 78, seg = tid / 78;
        int c0 = seg * 11;
        const float* c = &sC[r * 81 + c0];
        float acc[11] = {};
        #pragma unroll
        for (int i = 0; i < 25; ++i) {
            float v = c[i];                         // junk cols 78..79 -> only discarded accs
            #pragma unroll
            for (int k = 0; k < 15; ++k) {
                int j = i - k;
                if (j >= 0 && j < 11) acc[j] = fmaf(v, GW[k], acc[j]);
            }
        }
        float* d = &sD[r * 67 + c0];
        #pragma unroll
        for (int j = 0; j < 11; ++j)
            if (c0 + j < 64) d[j] = acc[j];
    }
    __syncthreads();

    // ---- V2 + softness + gradient mask -> out. 64 cols x 8 strips x 8 rows ----
    {
        int strip = tid >> 6, cc = tid & 63;
        int r0 = strip * 8;
        const float* d = &sD[r0 * 67 + cc];
        float acc[8] = {};
        #pragma unroll
        for (int i = 0; i < 22; ++i) {              // rows r0..r0+21 <= 77, all real
            float v = d[i * 67];
            #pragma unroll
            for (int k = 0; k < 15; ++k) {
                int j = i - k;
                if (j >= 0 && j < 8) acc[j] = fmaf(v, GW[k], acc[j]);
            }
        }
        float* __restrict__ op = out + (size_t)img * (HSZ * WSZ);
        const float yscale = 2.f / (float)(HSZ - 1);
        const float xscale = 2.f / (float)(WSZ - 1);
        const float mc = 1.f - 0.5f * itn;          // factor = mc + md*tanh(-hrd*gr/2)
        const float md = -0.5f * itn;
        const int gx = tx0 + cc;
        const float xn = fmaf((float)gx, xscale, -1.f);
        #pragma unroll
        for (int j = 0; j < 8; ++j) {
            int gy = ty0 + r0 + j;
            float x5c = sC[(r0 + j + 7) * 81 + cc + 7];
            float v = sof * acc[j] + (1.f - sof) * x5c;        // softness blend
            float yn = fmaf((float)gy, yscale, -1.f);
            float gr = xn * cst + yn * snt;
            float fac = fmaf(md, tanh_approx(-0.5f * hrd * gr), mc);  // 1 - itn*sigmoid(-hrd*gr)
            v = fminf(fmaxf(v * fac, 0.f), 1.f);
            op[gy * WSZ + gx] = v;
        }
    }
}

extern "C" void kernel_launch(void* const* d_in, const int* in_sizes, int n_in,
                              void* d_out, int out_size) {
    (void)in_sizes; (void)n_in; (void)out_size;

    static const int SMEM_BYTES = (7452 + 6318) * 4;          // 55,080
    cudaFuncSetAttribute(blur_kernel, cudaFuncAttributeMaxDynamicSharedMemorySize, SMEM_BYTES);

    pointwise_kernel<<<NPIX / 4 / 256, 256>>>(
        (const float*)d_in[0],  // x
        (const float*)d_in[1],  // gains
        (const float*)d_in[2],  // gamma
        (const float*)d_in[3],  // shadow_boost
        (const float*)d_in[4],  // highlight_reduce
        (const float*)d_in[5],  // brightness
        (const float*)d_in[6]); // contrast

    dim3 grid(WSZ / TILE, HSZ / TILE, NIMG);                  // 16 x 16 x 12 = 3072 CTAs
    blur_kernel<<<grid, 512, SMEM_BYTES>>>(
        (const float*)d_in[7],  // enhance_amount
        (const float*)d_in[8],  // softness
        (const float*)d_in[9],  // intensity
        (const float*)d_in[10], // rotation
        (const float*)d_in[11], // hardness
        (float*)d_out);
}

// round 11
// speedup vs baseline: 3.2233x; 3.2233x over previous
#include <cuda_runtime.h>
#include <math.h>

#define HSZ 1024
#define WSZ 1024
#define NIMG 12            // B*C = 4*3
#define TILE 64            // output tile (64x64), 512 threads
#define NPIX (NIMG * HSZ * WSZ)

// Scratch: pointwise-processed image x4 (after brightness/contrast). ~50MB,
// L2-resident for K2's center reads.
__device__ float g_x4[NPIX];

// ---------------------------------------------------------------------------
// Compile-time Gaussian weights (KSIZE=15, SIGMA=3) -> FFMA-imm literals.
// ---------------------------------------------------------------------------
__host__ __device__ constexpr double cexp_(double x) {
    double t = 1.0, s = 1.0;
    for (int i = 1; i < 60; ++i) { t *= x / i; s += t; }
    return s;
}
__host__ __device__ constexpr double gsum_() {
    double s = 0.0;
    for (int i = 0; i < 15; ++i) { double d = i - 7; s += cexp_(-d * d / 18.0); }
    return s;
}
__host__ __device__ constexpr float gw_(int k) {
    double d = k - 7; return (float)(cexp_(-d * d / 18.0) / gsum_());
}
#define GWDECL constexpr float GW[15] = {gw_(0), gw_(1), gw_(2),  gw_(3),  gw_(4),  \
    gw_(5),  gw_(6), gw_(7), gw_(8), gw_(9), gw_(10), gw_(11), gw_(12), gw_(13), gw_(14)}

__device__ __forceinline__ float tanh_approx(float x) {
    float y; asm("tanh.approx.f32 %0, %1;" : "=f"(y) : "f"(x));
    return y;
}

// ---------------------------------------------------------------------------
// K1: pointwise chain, 1x per pixel, float4 -> g_x4.
// ---------------------------------------------------------------------------
__global__ __launch_bounds__(256) void pointwise_kernel(
    const float* __restrict__ x, const float* __restrict__ gains,
    const float* __restrict__ p_gamma, const float* __restrict__ p_sb,
    const float* __restrict__ p_hr, const float* __restrict__ p_br,
    const float* __restrict__ p_ct)
{
    const int idx4 = blockIdx.x * 256 + threadIdx.x;
    const int ch   = (idx4 >> 18) % 3;
    const float gain = gains[ch];
    const float gam  = p_gamma[0];
    const float sbv  = p_sb[0], hrv = p_hr[0];
    const float shc  = -(sbv + hrv);
    const float brv  = p_br[0], ctv = p_ct[0];
    const float bc0  = 0.5f + brv;

    float4 v4 = __ldg((const float4*)x + idx4);
    float* v = &v4.x;
    #pragma unroll
    for (int i = 0; i < 4; ++i) {
        float t = __powf(v[i] * gain, gam);                   // WB + gamma
        float hi = fmaf(tanh_approx((t - 0.5f) * 5.f), 0.5f, 0.5f);
        t = fmaf(shc, hi, t + sbv);                           // shadow/highlight
        t = fminf(fmaxf(t, 0.f), 1.f);
        t = fmaf(ctv, t - 0.5f, bc0);                         // brightness/contrast
        v[i] = fminf(fmaxf(t, 0.f), 1.f);
    }
    ((float4*)g_x4)[idx4] = v4;
}

// ---------------------------------------------------------------------------
// K2: blur cascade per 64x64 tile. 512 threads, dynamic smem 64,768 B
// -> 3 CTAs/SM (48 warps). Buffer reuse:
//   region0 [0, 8740):      sA (92x95) during phase0/H1, then sC (78x81)
//   region1 [8740, 16192):  sB (92x81) during H1/V1,     then sD (78x67)
// sA is dead after H1 because the LCE center values are re-read from g_x4
// with COALESCED accesses (consecutive lanes = consecutive columns).
// Phases:
//   phase0: coalesced 92x92 halo copy g_x4 -> sA
//   H1: sA -> sB [92 x 78]     460 thr: r=tid%92 (row-fast, conflict-free)
//   V1+LCE: sB -> sC [78 x 78] 468 thr: col=tid%78; center from g_x4
//   H2: sC -> sD [78 x 64]     468 thr: r=tid%78
//   V2+softness+mask -> out    512 thr: 64 cols x 8 strips x 8 rows
// ---------------------------------------------------------------------------
__global__ __launch_bounds__(512, 3) void blur_kernel(
    const float* __restrict__ p_ea, const float* __restrict__ p_soft,
    const float* __restrict__ p_int, const float* __restrict__ p_rot,
    const float* __restrict__ p_hard, float* __restrict__ out)
{
    GWDECL;
    extern __shared__ float smem[];
    float* const sA = smem;                 // 92*95 = 8740
    float* const sC = smem;                 // 78*81 = 6318 (alias; sA dead after H1)
    float* const sB = smem + 8740;          // 92*81 = 7452
    float* const sD = smem + 8740;          // 78*67 = 5226 (alias; sB dead after V1)

    const int tid = threadIdx.x;
    const int img = blockIdx.z;
    const int ty0 = blockIdx.y * TILE;
    const int tx0 = blockIdx.x * TILE;

    const float eav = p_ea[0], sof = p_soft[0];
    const float itn = p_int[0], hrd = p_hard[0];
    float snt, cst;
    sincosf(p_rot[0] * 0.017453292519943295f, &snt, &cst);

    const float* __restrict__ xin = g_x4 + (size_t)img * (HSZ * WSZ);
    const bool interior = (ty0 >= 14) && (ty0 + 78 <= HSZ) && (tx0 >= 14) && (tx0 + 78 <= WSZ);

    // ---- phase 0: coalesced halo copy (zero-pad outside image) ----
    if (interior) {
        const float* __restrict__ base = xin + (ty0 - 14) * WSZ + (tx0 - 14);  // even col -> 8B aligned
        for (int p = tid; p < 92 * 46; p += 512) {
            int r = p / 46, m = p - r * 46;
            float2 v = __ldg((const float2*)(base + r * WSZ) + m);
            sA[r * 95 + 2 * m]     = v.x;
            sA[r * 95 + 2 * m + 1] = v.y;
        }
    } else {
        for (int p = tid; p < 92 * 92; p += 512) {
            int r = p / 92, c = p - r * 92;
            int gy = ty0 - 14 + r, gx = tx0 - 14 + c;
            float v = 0.f;
            if ((unsigned)gy < HSZ && (unsigned)gx < WSZ) v = __ldg(xin + gy * WSZ + gx);
            sA[r * 95 + c] = v;
        }
    }
    __syncthreads();

    // ---- H1: sA -> sB. row-fast lanes, 16 outputs/thread, window 30 ----
    if (tid < 460) {
        int r = tid % 92, seg = tid / 92;
        int c0 = seg * 16;
        const float* a = &sA[r * 95 + c0];
        float acc[16] = {};
        #pragma unroll
        for (int i = 0; i < 30; ++i) {
            float v = a[i];                         // cols >=92 junk -> only discarded accs
            #pragma unroll
            for (int k = 0; k < 15; ++k) {
                int j = i - k;
                if (j >= 0 && j < 16) acc[j] = fmaf(v, GW[k], acc[j]);
            }
        }
        float* b = &sB[r * 81 + c0];
        #pragma unroll
        for (int j = 0; j < 16; ++j)
            if (c0 + j < 78) b[j] = acc[j];
    }
    __syncthreads();   // also: everyone done reading sA before sC overwrites it

    // ---- V1 + LCE epilogue: sB -> sC (aliases sA). 13 rows/thread, window 27 ----
    if (tid < 468) {
        int strip = tid / 78, ccol = tid - 78 * strip;
        int r0 = strip * 13;
        const float* b = &sB[r0 * 81 + ccol];
        float acc[13] = {};
        #pragma unroll
        for (int i = 0; i < 27; ++i) {              // rows r0..r0+26 <= 91, all real
            float v = b[i * 81];
            #pragma unroll
            for (int k = 0; k < 15; ++k) {
                int j = i - k;
                if (j >= 0 && j < 13) acc[j] = fmaf(v, GW[k], acc[j]);
            }
        }
        if (interior) {
            const float* __restrict__ ctr = xin + (ty0 - 7 + r0) * WSZ + (tx0 - 7 + ccol);
            #pragma unroll
            for (int j = 0; j < 13; ++j) {
                float a = __ldg(ctr + j * WSZ);     // coalesced: lanes = consecutive cols
                sC[(r0 + j) * 81 + ccol] = fmaf(eav, a - acc[j], a);  // x + ea*(x - mean)
            }
        } else {
            #pragma unroll
            for (int j = 0; j < 13; ++j) {
                int rr = r0 + j;
                int gy = ty0 - 7 + rr, gx = tx0 - 7 + ccol;
                float val = 0.f;
                if ((unsigned)gy < HSZ && (unsigned)gx < WSZ) {
                    float a = __ldg(xin + gy * WSZ + gx);
                    val = fmaf(eav, a - acc[j], a);
                }
                sC[rr * 81 + ccol] = val;           // zero outside image = blur2 zero-pad
            }
        }
    }
    __syncthreads();

    // ---- H2: sC -> sD (aliases sB). row-fast lanes, 11 outputs/thread, window 25 ----
    if (tid < 468) {
        int r = tid % 78, seg = tid / 78;
        int c0 = seg * 11;
        const float* c = &sC[r * 81 + c0];
        float acc[11] = {};
        #pragma unroll
        for (int i = 0; i < 25; ++i) {
            float v = c[i];                         // junk cols 78..79 -> only discarded accs
            #pragma unroll
            for (int k = 0; k < 15; ++k) {
                int j = i - k;
                if (j >= 0 && j < 11) acc[j] = fmaf(v, GW[k], acc[j]);
            }
        }
        float* d = &sD[r * 67 + c0];
        #pragma unroll
        for (int j = 0; j < 11; ++j)
            if (c0 + j < 64) d[j] = acc[j];
    }
    __syncthreads();

    // ---- V2 + softness + gradient mask -> out. 64 cols x 8 strips x 8 rows ----
    {
        int strip = tid >> 6, cc = tid & 63;
        int r0 = strip * 8;
        const float* d = &sD[r0 * 67 + cc];
        float acc[8] = {};
        #pragma unroll
        for (int i = 0; i < 22; ++i) {              // rows r0..r0+21 <= 77, all real
            float v = d[i * 67];
            #pragma unroll
            for (int k = 0; k < 15; ++k) {
                int j = i - k;
                if (j >= 0 && j < 8) acc[j] = fmaf(v, GW[k], acc[j]);
            }
        }
        float* __restrict__ op = out + (size_t)img * (HSZ * WSZ);
        const float yscale = 2.f / (float)(HSZ - 1);
        const float xscale = 2.f / (float)(WSZ - 1);
        const float mc = 1.f - 0.5f * itn;          // factor = mc + md*tanh(-hrd*gr/2)
        const float md = -0.5f * itn;
        const int gx = tx0 + cc;
        const float xn = fmaf((float)gx, xscale, -1.f);
        #pragma unroll
        for (int j = 0; j < 8; ++j) {
            int gy = ty0 + r0 + j;
            float x5c = sC[(r0 + j + 7) * 81 + cc + 7];
            float v = sof * acc[j] + (1.f - sof) * x5c;        // softness blend
            float yn = fmaf((float)gy, yscale, -1.f);
            float gr = xn * cst + yn * snt;
            float fac = fmaf(md, tanh_approx(-0.5f * hrd * gr), mc);  // 1 - itn*sigmoid(-hrd*gr)
            v = fminf(fmaxf(v * fac, 0.f), 1.f);
            op[gy * WSZ + gx] = v;
        }
    }
}

extern "C" void kernel_launch(void* const* d_in, const int* in_sizes, int n_in,
                              void* d_out, int out_size) {
    (void)in_sizes; (void)n_in; (void)out_size;

    static const int SMEM_BYTES = (8740 + 7452) * 4;          // 64,768
    cudaFuncSetAttribute(blur_kernel, cudaFuncAttributeMaxDynamicSharedMemorySize, SMEM_BYTES);

    pointwise_kernel<<<NPIX / 4 / 256, 256>>>(
        (const float*)d_in[0],  // x
        (const float*)d_in[1],  // gains
        (const float*)d_in[2],  // gamma
        (const float*)d_in[3],  // shadow_boost
        (const float*)d_in[4],  // highlight_reduce
        (const float*)d_in[5],  // brightness
        (const float*)d_in[6]); // contrast

    dim3 grid(WSZ / TILE, HSZ / TILE, NIMG);                  // 16 x 16 x 12 = 3072 CTAs
    blur_kernel<<<grid, 512, SMEM_BYTES>>>(
        (const float*)d_in[7],  // enhance_amount
        (const float*)d_in[8],  // softness
        (const float*)d_in[9],  // intensity
        (const float*)d_in[10], // rotation
        (const float*)d_in[11], // hardness
        (float*)d_out);
}